// round 13
// baseline (speedup 1.0000x reference)
#include <cuda_runtime.h>

#define NQ   14
#define EPB  8           // batch elements per 32-thread block (4 lanes each)
#define TPB  32          // single-warp CTAs: minimal launch/setup serialization

// Transfer-matrix contraction of the 14-qubit 2-layer RY+CNOT-ring circuit.
// 4 lanes per batch element (one per boundary branch of qubit 0). All
// cross-lane exchange is width-4 warp shuffles: no smem, no barriers.
__global__ __launch_bounds__(TPB)
void qnn_warp_kernel(const float* __restrict__ x,
                     const float* __restrict__ wt,
                     float* __restrict__ out, int B)
{
    const int tid  = threadIdx.x;
    const int e    = blockIdx.x * EPB + (tid >> 2);
    const int br   = tid & 3;
    const bool live = (e < B);

    // ---- front-batch ALL global loads (overlap latency with MUFU below) ----
    float xv[4], w0v[4], w1v[4];
    #pragma unroll
    for (int i = 0; i < 4; ++i) {
        const int q = 4 * i + br;
        const bool qok = (q < NQ);
        xv[i]  = (qok && live) ? __ldg(&x[e * NQ + q]) : 0.0f;
        w0v[i] = qok ? __ldg(&wt[q])      : 0.0f;
        w1v[i] = qok ? __ldg(&wt[NQ + q]) : 0.0f;
    }

    // ---- per-lane trig for sites q = 4i + br (alpha and layer-1 weights) ----
    float axc[4], axs[4], wtc[4], wtsn[4];
    #pragma unroll
    for (int i = 0; i < 4; ++i) {
        __sincosf(0.5f * (xv[i] + w0v[i]), &axs[i], &axc[i]);
        __sincosf(w1v[i], &wtsn[i], &wtc[i]);
    }

    // ---- quad-shuffle gather: all 14 sites' coefficients into registers ----
    float ca[NQ], sa[NQ], cw[NQ], sw[NQ];
    #pragma unroll
    for (int w = 0; w < NQ; ++w) {
        const int i = w >> 2, l = w & 3;
        ca[w] = __shfl_sync(0xffffffffu, axc[i],  l, 4);
        sa[w] = __shfl_sync(0xffffffffu, axs[i],  l, 4);
        cw[w] = __shfl_sync(0xffffffffu, wtc[i],  l, 4);
        sw[w] = __shfl_sync(0xffffffffu, wtsn[i], l, 4);
    }

    // Doubles: s2 = sin(2a); suffix products cg[w] = prod_{k>w} cos(2a_k)
    float s2[NQ], cg[NQ];
    #pragma unroll
    for (int w = 0; w < NQ; ++w) s2[w] = 2.0f * ca[w] * sa[w];
    {
        float p = 1.0f;
        cg[NQ - 1] = 1.0f;
        #pragma unroll
        for (int q = NQ - 2; q >= 1; --q) {
            p *= ca[q + 1] * ca[q + 1] - sa[q + 1] * sa[q + 1];
            cg[q] = p;
        }
    }

    const bool  diag  = (br == 0) || (br == 3);
    const float sgn_d = (br == 0) ? 1.0f : -1.0f;
    const float ct0 = cw[0], st0 = sw[0];

    // ---- branch chain (verbatim verified math) ----
    const float c0 = ca[0], s0 = sa[0];
    float r0 = (br == 0) ? c0 * c0 : 0.0f;
    float r1 = (br == 1) ? c0 * s0 : 0.0f;
    float r2 = (br == 2) ? c0 * s0 : 0.0f;
    float r3 = (br == 3) ? s0 * s0 : 0.0f;

    float Ev[NQ];

    #pragma unroll
    for (int w = 1; w < NQ; ++w) {
        const float c  = ca[w], s  = sa[w];
        const float ct = cw[w], st = sw[w];
        float t0 = c * r0 + s * r2, t1 = c * r1 + s * r3;
        float t2 = c * r2 + s * r0, t3 = c * r3 + s * r1;
        float u0 = c * t0 + s * t1, u1 = c * t1 + s * t0;
        float u2 = c * t2 + s * t3, u3 = c * t3 + s * t2;
        r0 =  ct * u0; r1 = -st * u1; r2 = -st * u2; r3 = -ct * u3;
        if (w <= NQ - 2) {
            Ev[w] = diag
                ? (sgn_d * ct0) * cg[w] * (r0 - r3)
                : -st0 * ((r0 + r3) + s2[w + 1] * (r1 + r2));
        }
    }
    {
        float v13;
        if (br == 0)      v13 =  ct0 * (r0 - r3) - st0 * (r1 + r2);
        else if (br == 3) v13 = -ct0 * (r0 - r3) - st0 * (r1 + r2);
        else if (br == 1) v13 = -st0 * (r0 + r3) + ct0 * (r1 - r2);
        else              v13 = -st0 * (r0 + r3) - ct0 * (r1 - r2);
        Ev[NQ - 1] = v13;                        // wire 13
        Ev[0] = diag ? (r0 + r3) : (r1 + r2);    // wire 0 (identity site op)
    }

    // ---- 4-way branch sum via quad butterflies; quad-coalesced store ----
    #pragma unroll
    for (int w = 0; w < NQ; ++w) {
        float v = Ev[w];
        v += __shfl_xor_sync(0xffffffffu, v, 1, 4);
        v += __shfl_xor_sync(0xffffffffu, v, 2, 4);
        Ev[w] = v;
    }
    if (live) {
        #pragma unroll
        for (int i = 0; i < 4; ++i) {
            const int q = 4 * i + br;
            if (q < NQ) out[e * NQ + q] = Ev[q];
        }
    }
}

extern "C" void kernel_launch(void* const* d_in, const int* in_sizes, int n_in,
                              void* d_out, int out_size)
{
    const float* x  = (const float*)d_in[0];   // (B, 14) fp32
    const float* wt = (const float*)d_in[1];   // (2, 14) fp32
    float* out = (float*)d_out;                // (B, 14) fp32

    const int B = in_sizes[0] / NQ;
    qnn_warp_kernel<<<(B + EPB - 1) / EPB, TPB>>>(x, wt, out, B);
}

// round 14
// speedup vs baseline: 1.2374x; 1.2374x over previous
#include <cuda_runtime.h>

#define NQ   14
#define EPB  32          // batch elements per block
#define TPB  128         // 4 lanes (branches) per element; 4 warps/CTA (measured best)

// Transfer-matrix contraction of the 14-qubit 2-layer RY+CNOT-ring circuit.
// 4 lanes per batch element (one per boundary branch of qubit 0). All
// cross-lane exchange is width-4 warp shuffles: no smem, no barriers.
__global__ __launch_bounds__(TPB)
void qnn_warp_kernel(const float* __restrict__ x,
                     const float* __restrict__ wt,
                     float* __restrict__ out, int B)
{
    const int tid  = threadIdx.x;
    const int e    = blockIdx.x * EPB + (tid >> 2);
    const int br   = tid & 3;
    const bool live = (e < B);

    // ---- front-batch ALL global loads (overlap LDG latency with MUFU) ----
    float xv[4], w0v[4], w1v[4];
    #pragma unroll
    for (int i = 0; i < 4; ++i) {
        const int q = 4 * i + br;
        const bool qok = (q < NQ);
        xv[i]  = (qok && live) ? __ldg(&x[e * NQ + q]) : 0.0f;
        w0v[i] = qok ? __ldg(&wt[q])      : 0.0f;
        w1v[i] = qok ? __ldg(&wt[NQ + q]) : 0.0f;
    }

    // ---- per-lane trig for sites q = 4i + br (alpha and layer-1 weights) ----
    float axc[4], axs[4], wtc[4], wtsn[4];
    #pragma unroll
    for (int i = 0; i < 4; ++i) {
        __sincosf(0.5f * (xv[i] + w0v[i]), &axs[i], &axc[i]);
        __sincosf(w1v[i], &wtsn[i], &wtc[i]);
    }

    // ---- quad-shuffle gather: all 14 sites' coefficients into registers ----
    float ca[NQ], sa[NQ], cw[NQ], sw[NQ];
    #pragma unroll
    for (int w = 0; w < NQ; ++w) {
        const int i = w >> 2, l = w & 3;
        ca[w] = __shfl_sync(0xffffffffu, axc[i],  l, 4);
        sa[w] = __shfl_sync(0xffffffffu, axs[i],  l, 4);
        cw[w] = __shfl_sync(0xffffffffu, wtc[i],  l, 4);
        sw[w] = __shfl_sync(0xffffffffu, wtsn[i], l, 4);
    }

    // Doubles: s2 = sin(2a); suffix products cg[w] = prod_{k>w} cos(2a_k)
    float s2[NQ], cg[NQ];
    #pragma unroll
    for (int w = 0; w < NQ; ++w) s2[w] = 2.0f * ca[w] * sa[w];
    {
        float p = 1.0f;
        cg[NQ - 1] = 1.0f;
        #pragma unroll
        for (int q = NQ - 2; q >= 1; --q) {
            p *= ca[q + 1] * ca[q + 1] - sa[q + 1] * sa[q + 1];
            cg[q] = p;
        }
    }

    const bool  diag  = (br == 0) || (br == 3);
    const float sgn_d = (br == 0) ? 1.0f : -1.0f;
    const float ct0 = cw[0], st0 = sw[0];

    // ---- branch chain (verbatim verified math) ----
    const float c0 = ca[0], s0 = sa[0];
    float r0 = (br == 0) ? c0 * c0 : 0.0f;
    float r1 = (br == 1) ? c0 * s0 : 0.0f;
    float r2 = (br == 2) ? c0 * s0 : 0.0f;
    float r3 = (br == 3) ? s0 * s0 : 0.0f;

    float Ev[NQ];

    #pragma unroll
    for (int w = 1; w < NQ; ++w) {
        const float c  = ca[w], s  = sa[w];
        const float ct = cw[w], st = sw[w];
        float t0 = c * r0 + s * r2, t1 = c * r1 + s * r3;
        float t2 = c * r2 + s * r0, t3 = c * r3 + s * r1;
        float u0 = c * t0 + s * t1, u1 = c * t1 + s * t0;
        float u2 = c * t2 + s * t3, u3 = c * t3 + s * t2;
        r0 =  ct * u0; r1 = -st * u1; r2 = -st * u2; r3 = -ct * u3;
        if (w <= NQ - 2) {
            Ev[w] = diag
                ? (sgn_d * ct0) * cg[w] * (r0 - r3)
                : -st0 * ((r0 + r3) + s2[w + 1] * (r1 + r2));
        }
    }
    {
        float v13;
        if (br == 0)      v13 =  ct0 * (r0 - r3) - st0 * (r1 + r2);
        else if (br == 3) v13 = -ct0 * (r0 - r3) - st0 * (r1 + r2);
        else if (br == 1) v13 = -st0 * (r0 + r3) + ct0 * (r1 - r2);
        else              v13 = -st0 * (r0 + r3) - ct0 * (r1 - r2);
        Ev[NQ - 1] = v13;                        // wire 13
        Ev[0] = diag ? (r0 + r3) : (r1 + r2);    // wire 0 (identity site op)
    }

    // ---- 4-way branch sum via quad butterflies; quad-coalesced store ----
    #pragma unroll
    for (int w = 0; w < NQ; ++w) {
        float v = Ev[w];
        v += __shfl_xor_sync(0xffffffffu, v, 1, 4);
        v += __shfl_xor_sync(0xffffffffu, v, 2, 4);
        Ev[w] = v;
    }
    if (live) {
        #pragma unroll
        for (int i = 0; i < 4; ++i) {
            const int q = 4 * i + br;
            if (q < NQ) out[e * NQ + q] = Ev[q];
        }
    }
}

extern "C" void kernel_launch(void* const* d_in, const int* in_sizes, int n_in,
                              void* d_out, int out_size)
{
    const float* x  = (const float*)d_in[0];   // (B, 14) fp32
    const float* wt = (const float*)d_in[1];   // (2, 14) fp32
    float* out = (float*)d_out;                // (B, 14) fp32

    const int B = in_sizes[0] / NQ;
    qnn_warp_kernel<<<(B + EPB - 1) / EPB, TPB>>>(x, wt, out, B);
}